// round 17
// baseline (speedup 1.0000x reference)
#include <cuda_runtime.h>
#include <cuda_bf16.h>
#include <cuda_pipeline.h>
#include <mma.h>
#include <math.h>

using namespace nvcuda;

#define B_     16
#define P_     1024
#define E_     768
#define HID_   768
#define HEADS_ 12
#define T3_    2304
#define BP_    (B_*P_)
#define PE_    (P_*E_)
#define EE_    (E_*E_)
#define NSTREAM 8
#define BG_    (B_/NSTREAM)

#define RSTG   37888
#define ROW_SMEM (3*RSTG)
#define CSTG   34816
#define COL_SMEM (3*CSTG)

// ---------------- scratch ----------------
__device__ float g_part[B_][128][2];
__device__ float g_stats[B_][2];
__device__ __nv_bfloat16 g_xh[(size_t)BP_*E_];
__device__ __nv_bfloat16 g_xl[(size_t)BP_*E_];
__device__ __nv_bfloat16 g_wqh[(size_t)EE_];
__device__ __nv_bfloat16 g_wql[(size_t)EE_];
__device__ __nv_bfloat16 g_wvh[(size_t)EE_];
__device__ __nv_bfloat16 g_wvl[(size_t)EE_];
__device__ __nv_bfloat16 g_wkth[(size_t)EE_];
__device__ __nv_bfloat16 g_wktl[(size_t)EE_];
__device__ __nv_bfloat16 g_gh[(size_t)B_*EE_];
__device__ __nv_bfloat16 g_gl[(size_t)B_*EE_];
__device__ __nv_bfloat16 g_zh[(size_t)B_*EE_];
__device__ __nv_bfloat16 g_zl[(size_t)B_*EE_];
__device__ __nv_bfloat16 g_nh[(size_t)B_*EE_];
__device__ __nv_bfloat16 g_nl[(size_t)B_*EE_];
__device__ __nv_bfloat16 g_ch[(size_t)B_*EE_];
__device__ __nv_bfloat16 g_cl[(size_t)B_*EE_];

// ---------------- helpers ----------------
__device__ __forceinline__ void bsplit(float f, __nv_bfloat16 &h, __nv_bfloat16 &l) {
    h = __float2bfloat16_rn(f);
    l = __float2bfloat16_rn(f - __bfloat162float(h));
}
__device__ __forceinline__ void split_store_g(__nv_bfloat16* ph, __nv_bfloat16* pl, float4 v) {
    __nv_bfloat16 h0,h1,h2,h3,l0,l1,l2,l3;
    bsplit(v.x,h0,l0); bsplit(v.y,h1,l1); bsplit(v.z,h2,l2); bsplit(v.w,h3,l3);
    *(__nv_bfloat162*)(ph+0) = __halves2bfloat162(h0,h1);
    *(__nv_bfloat162*)(ph+2) = __halves2bfloat162(h2,h3);
    *(__nv_bfloat162*)(pl+0) = __halves2bfloat162(l0,l1);
    *(__nv_bfloat162*)(pl+2) = __halves2bfloat162(l2,l3);
}

typedef wmma::fragment<wmma::matrix_a, 16, 16, 16, __nv_bfloat16, wmma::row_major> FragA;
typedef wmma::fragment<wmma::matrix_a, 16, 16, 16, __nv_bfloat16, wmma::col_major> FragAc;
typedef wmma::fragment<wmma::matrix_b, 16, 16, 16, __nv_bfloat16, wmma::row_major> FragB;
typedef wmma::fragment<wmma::accumulator, 16, 16, 16, float> FragC;

__device__ __forceinline__ void frag_split_store2(
    const FragC& f, float* epiw, int lane,
    __nv_bfloat16* Ch, __nv_bfloat16* Cl, int ldc,
    int grow, int gcol, int mirror) {
    wmma::store_matrix_sync(epiw, f, 16, wmma::mem_row_major);
    __syncwarp();
    int er = lane >> 1, ec = (lane & 1)*8;
    const float* ep = epiw + er*16 + ec;
    float4 v0 = make_float4(ep[0], ep[1], ep[2], ep[3]);
    float4 v1 = make_float4(ep[4], ep[5], ep[6], ep[7]);
    size_t o = (size_t)(grow + er)*ldc + gcol + ec;
    split_store_g(Ch + o,     Cl + o,     v0);
    split_store_g(Ch + o + 4, Cl + o + 4, v1);
    if (mirror) {
        float4 t0, t1;
        t0.x = epiw[(ec+0)*16 + er]; t0.y = epiw[(ec+1)*16 + er];
        t0.z = epiw[(ec+2)*16 + er]; t0.w = epiw[(ec+3)*16 + er];
        t1.x = epiw[(ec+4)*16 + er]; t1.y = epiw[(ec+5)*16 + er];
        t1.z = epiw[(ec+6)*16 + er]; t1.w = epiw[(ec+7)*16 + er];
        size_t om = (size_t)(gcol + er)*ldc + grow + ec;
        split_store_g(Ch + om,     Cl + om,     t0);
        split_store_g(Ch + om + 4, Cl + om + 4, t1);
    }
    __syncwarp();
}
__device__ __forceinline__ void frag_split_store(
    const FragC& f, float* epiw, int lane,
    __nv_bfloat16* Ch, __nv_bfloat16* Cl, int ldc, int grow, int gcol) {
    frag_split_store2(f, epiw, lane, Ch, Cl, ldc, grow, gcol, 0);
}

// ---------------- stage fills ----------------
__device__ __forceinline__ void fill_row(
    char* sm, int stg,
    const __nv_bfloat16* pAh, const __nv_bfloat16* pAl,
    const __nv_bfloat16* pBh, const __nv_bfloat16* pBl,
    int lda, int ldb, int k0, int tid)
{
    char* base = sm + stg*RSTG;
    __nv_bfloat16* Ah = (__nv_bfloat16*)(base);
    __nv_bfloat16* Al = (__nv_bfloat16*)(base + 10240);
    __nv_bfloat16* Bh = (__nv_bfloat16*)(base + 20480);
    __nv_bfloat16* Bl = (__nv_bfloat16*)(base + 29184);
    for (int i = 0; i < 8; i++) {
        int id = tid + i*128;
        int row = id >> 3, seg = id & 7;
        int c = (seg & 3)*8;
        if (seg < 4)
            __pipeline_memcpy_async(Ah + row*40 + c, pAh + (size_t)row*lda + k0 + c, 16);
        else
            __pipeline_memcpy_async(Al + row*40 + c, pAl + (size_t)row*lda + k0 + c, 16);
    }
    for (int i = 0; i < 8; i++) {
        int id = tid + i*128;
        int mat = id >> 9, rem = id & 511;
        int kr = rem >> 4, c = (rem & 15)*8;
        if (mat == 0)
            __pipeline_memcpy_async(Bh + kr*136 + c, pBh + (size_t)(k0+kr)*ldb + c, 16);
        else
            __pipeline_memcpy_async(Bl + kr*136 + c, pBl + (size_t)(k0+kr)*ldb + c, 16);
    }
}

__device__ __forceinline__ void fill_col(
    char* sm, int stg,
    const __nv_bfloat16* pAh, const __nv_bfloat16* pAl,
    const __nv_bfloat16* pBh, const __nv_bfloat16* pBl,
    int lda, int ldb, int k0, int tid)
{
    char* base = sm + stg*CSTG;
    __nv_bfloat16* Ah = (__nv_bfloat16*)(base);
    __nv_bfloat16* Al = (__nv_bfloat16*)(base + 8704);
    __nv_bfloat16* Bh = (__nv_bfloat16*)(base + 17408);
    __nv_bfloat16* Bl = (__nv_bfloat16*)(base + 26112);
    for (int i = 0; i < 8; i++) {
        int id = tid + i*128;
        int mat = id >> 9, rem = id & 511;
        int kr = rem >> 4, c = (rem & 15)*8;
        if (mat == 0)
            __pipeline_memcpy_async(Ah + kr*136 + c, pAh + (size_t)(k0+kr)*lda + c, 16);
        else
            __pipeline_memcpy_async(Al + kr*136 + c, pAl + (size_t)(k0+kr)*lda + c, 16);
    }
    for (int i = 0; i < 8; i++) {
        int id = tid + i*128;
        int mat = id >> 9, rem = id & 511;
        int kr = rem >> 4, c = (rem & 15)*8;
        if (mat == 0)
            __pipeline_memcpy_async(Bh + kr*136 + c, pBh + (size_t)(k0+kr)*ldb + c, 16);
        else
            __pipeline_memcpy_async(Bl + kr*136 + c, pBl + (size_t)(k0+kr)*ldb + c, 16);
    }
}

// ---------------- cores: 3-stage ring, one barrier/iter ----------------
__device__ __forceinline__ void core_row(
    char* sm, FragC fc[4][4],
    const __nv_bfloat16* pAh, const __nv_bfloat16* pAl,
    const __nv_bfloat16* pBh, const __nv_bfloat16* pBl,
    int lda, int ldb, int nit)
{
    const int tid = threadIdx.x, wid = tid >> 5;
    const int wm = (wid >> 1)*64, wn = (wid & 1)*64;
    for (int i = 0; i < 4; i++)
        for (int j = 0; j < 4; j++)
            wmma::fill_fragment(fc[i][j], 0.f);

    fill_row(sm, 0, pAh, pAl, pBh, pBl, lda, ldb, 0, tid);
    __pipeline_commit();

    int cur = 0, nxt = 1;
    for (int it = 0; it < nit; it++) {
        if (it + 1 < nit) {
            fill_row(sm, nxt, pAh, pAl, pBh, pBl, lda, ldb, (it+1)*32, tid);
            __pipeline_commit();
            __pipeline_wait_prior(1);
        } else {
            __pipeline_wait_prior(0);
        }
        __syncthreads();
        char* base = sm + cur*RSTG;
        __nv_bfloat16* Ah = (__nv_bfloat16*)(base);
        __nv_bfloat16* Al = (__nv_bfloat16*)(base + 10240);
        __nv_bfloat16* Bh = (__nv_bfloat16*)(base + 20480);
        __nv_bfloat16* Bl = (__nv_bfloat16*)(base + 29184);
        for (int ks = 0; ks < 2; ks++) {
            FragB fbh[4], fbl[4];
            for (int nj = 0; nj < 4; nj++) {
                wmma::load_matrix_sync(fbh[nj], Bh + ks*16*136 + wn + nj*16, 136);
                wmma::load_matrix_sync(fbl[nj], Bl + ks*16*136 + wn + nj*16, 136);
            }
            for (int mi = 0; mi < 4; mi++) {
                FragA fah, fal;
                wmma::load_matrix_sync(fah, Ah + (wm + mi*16)*40 + ks*16, 40);
                wmma::load_matrix_sync(fal, Al + (wm + mi*16)*40 + ks*16, 40);
                for (int nj = 0; nj < 4; nj++) {
                    wmma::mma_sync(fc[mi][nj], fah, fbh[nj], fc[mi][nj]);
                    wmma::mma_sync(fc[mi][nj], fah, fbl[nj], fc[mi][nj]);
                    wmma::mma_sync(fc[mi][nj], fal, fbh[nj], fc[mi][nj]);
                }
            }
        }
        cur = nxt;
        nxt = (nxt == 2) ? 0 : (nxt + 1);
    }
    __syncthreads();
}

__device__ __forceinline__ void core_col(
    char* sm, FragC fc[4][4],
    const __nv_bfloat16* pAh, const __nv_bfloat16* pAl,
    const __nv_bfloat16* pBh, const __nv_bfloat16* pBl,
    int lda, int ldb, int nit)
{
    const int tid = threadIdx.x, wid = tid >> 5;
    const int wm = (wid >> 1)*64, wn = (wid & 1)*64;
    for (int i = 0; i < 4; i++)
        for (int j = 0; j < 4; j++)
            wmma::fill_fragment(fc[i][j], 0.f);

    fill_col(sm, 0, pAh, pAl, pBh, pBl, lda, ldb, 0, tid);
    __pipeline_commit();

    int cur = 0, nxt = 1;
    for (int it = 0; it < nit; it++) {
        if (it + 1 < nit) {
            fill_col(sm, nxt, pAh, pAl, pBh, pBl, lda, ldb, (it+1)*32, tid);
            __pipeline_commit();
            __pipeline_wait_prior(1);
        } else {
            __pipeline_wait_prior(0);
        }
        __syncthreads();
        char* base = sm + cur*CSTG;
        __nv_bfloat16* Ah = (__nv_bfloat16*)(base);
        __nv_bfloat16* Al = (__nv_bfloat16*)(base + 8704);
        __nv_bfloat16* Bh = (__nv_bfloat16*)(base + 17408);
        __nv_bfloat16* Bl = (__nv_bfloat16*)(base + 26112);
        for (int ks = 0; ks < 2; ks++) {
            FragB fbh[4], fbl[4];
            for (int nj = 0; nj < 4; nj++) {
                wmma::load_matrix_sync(fbh[nj], Bh + ks*16*136 + wn + nj*16, 136);
                wmma::load_matrix_sync(fbl[nj], Bl + ks*16*136 + wn + nj*16, 136);
            }
            for (int mi = 0; mi < 4; mi++) {
                FragAc fah, fal;
                wmma::load_matrix_sync(fah, Ah + ks*16*136 + wm + mi*16, 136);
                wmma::load_matrix_sync(fal, Al + ks*16*136 + wm + mi*16, 136);
                for (int nj = 0; nj < 4; nj++) {
                    wmma::mma_sync(fc[mi][nj], fah, fbh[nj], fc[mi][nj]);
                    wmma::mma_sync(fc[mi][nj], fah, fbl[nj], fc[mi][nj]);
                    wmma::mma_sync(fc[mi][nj], fal, fbh[nj], fc[mi][nj]);
                }
            }
        }
        cur = nxt;
        nxt = (nxt == 2) ? 0 : (nxt + 1);
    }
    __syncthreads();
}

// ---------------- small kernels (per-group) ----------------
__global__ void ln_stats1(const float* __restrict__ x, int boff) {
    int b = boff + blockIdx.y, c = blockIdx.x;
    const int CH = PE_ / 128;
    const float4* xb = (const float4*)(x + (size_t)b*PE_ + (size_t)c*CH);
    float s = 0.f, s2 = 0.f;
    for (int i = threadIdx.x; i < CH/4; i += 256) {
        float4 v = xb[i];
        s  += v.x + v.y + v.z + v.w;
        s2 += v.x*v.x + v.y*v.y + v.z*v.z + v.w*v.w;
    }
    __shared__ float sh[2][8];
    for (int o = 16; o; o >>= 1) {
        s  += __shfl_down_sync(0xffffffffu, s,  o);
        s2 += __shfl_down_sync(0xffffffffu, s2, o);
    }
    if ((threadIdx.x & 31) == 0) { sh[0][threadIdx.x>>5] = s; sh[1][threadIdx.x>>5] = s2; }
    __syncthreads();
    if (threadIdx.x == 0) {
        float a = 0.f, a2 = 0.f;
        for (int i = 0; i < 8; i++) { a += sh[0][i]; a2 += sh[1][i]; }
        g_part[b][c][0] = a; g_part[b][c][1] = a2;
    }
}

__global__ void ln_stats2(int boff) {
    int b = boff + blockIdx.x, t = threadIdx.x;
    __shared__ float sh[2][128];
    sh[0][t] = g_part[b][t][0];
    sh[1][t] = g_part[b][t][1];
    __syncthreads();
    for (int o = 64; o; o >>= 1) {
        if (t < o) { sh[0][t] += sh[0][t+o]; sh[1][t] += sh[1][t+o]; }
        __syncthreads();
    }
    if (t == 0) {
        float m   = sh[0][0] / (float)PE_;
        float var = sh[1][0] / (float)PE_ - m*m;
        g_stats[b][0] = m;
        g_stats[b][1] = rsqrtf(var + 1e-5f);
    }
}

__global__ void split_xn(const float* __restrict__ x, const float* __restrict__ lnw,
                         const float* __restrict__ lnb, int boff) {
    int b = boff + blockIdx.y;
    float m = g_stats[b][0], r = g_stats[b][1];
    const int n4 = PE_/4;
    for (int i = blockIdx.x*256 + threadIdx.x; i < n4; i += 96*256) {
        int p   = i / (E_/4);
        int col = (i - p*(E_/4))*4;
        float4 xv = *(const float4*)(x   + (size_t)b*PE_ + (size_t)i*4);
        float4 wv = *(const float4*)(lnw + (size_t)p*E_ + col);
        float4 bv = *(const float4*)(lnb + (size_t)p*E_ + col);
        float4 d;
        d.x = (xv.x - m)*r*wv.x + bv.x;
        d.y = (xv.y - m)*r*wv.y + bv.y;
        d.z = (xv.z - m)*r*wv.z + bv.z;
        d.w = (xv.w - m)*r*wv.w + bv.w;
        split_store_g(g_xh + (size_t)b*PE_ + (size_t)i*4,
                      g_xl + (size_t)b*PE_ + (size_t)i*4, d);
    }
}

__global__ void split_w_all(const float* __restrict__ qkv) {
    int i = blockIdx.x*256 + threadIdx.x;
    if (i >= EE_/4) return;
    int which = blockIdx.y;
    if (which == 0) {
        int e  = i / (E_/4);
        int hq = (i - e*(E_/4))*4;
        int c  = (hq >> 6)*192 + (hq & 63);
        float4 v = *(const float4*)(qkv + (size_t)e*T3_ + c);
        size_t o = (size_t)e*E_ + hq;
        split_store_g(g_wqh + o, g_wql + o, v);
    } else if (which == 1) {
        int e  = i / (E_/4);
        int hv = (i - e*(E_/4))*4;
        int c  = (hv >> 6)*192 + 128 + (hv & 63);
        float4 v = *(const float4*)(qkv + (size_t)e*T3_ + c);
        size_t o = (size_t)e*E_ + hv;
        split_store_g(g_wvh + o, g_wvl + o, v);
    } else {
        int hk = i / (E_/4);
        int e4 = (i - hk*(E_/4))*4;
        int c  = (hk >> 6)*192 + 64 + (hk & 63);
        float4 v;
        v.x = qkv[(size_t)(e4+0)*T3_ + c];
        v.y = qkv[(size_t)(e4+1)*T3_ + c];
        v.z = qkv[(size_t)(e4+2)*T3_ + c];
        v.w = qkv[(size_t)(e4+3)*T3_ + c];
        size_t o = (size_t)hk*E_ + e4;
        split_store_g(g_wkth + o, g_wktl + o, v);
    }
}

// ---------------- GEMM chain kernels (per batch-group) ----------------
__global__ __launch_bounds__(128) void tc_gram(int boff) {
    extern __shared__ char sm[];
    const int b = boff + blockIdx.z;
    int t = blockIdx.x;
    int ti = 0;
    while (t > ti) { t -= ti + 1; ti++; }
    const int tj = t;
    const int bm = ti*128, bn = tj*128;
    const __nv_bfloat16* xh = g_xh + (size_t)b*PE_;
    const __nv_bfloat16* xl = g_xl + (size_t)b*PE_;
    FragC fc[4][4];
    core_col(sm, fc, xh + bm, xl + bm, xh + bn, xl + bn, E_, E_, P_/32);
    const int lane = threadIdx.x & 31, wid = threadIdx.x >> 5;
    const int wm = (wid >> 1)*64, wn = (wid & 1)*64;
    float* epi = (float*)sm + wid*256;
    __nv_bfloat16* Ch = g_gh + (size_t)b*EE_;
    __nv_bfloat16* Cl = g_gl + (size_t)b*EE_;
    const int mirror = (bm != bn);
    for (int mi = 0; mi < 4; mi++)
        for (int nj = 0; nj < 4; nj++)
            frag_split_store2(fc[mi][nj], epi, lane, Ch, Cl, E_,
                              bm + wm + mi*16, bn + wn + nj*16, mirror);
}

__global__ __launch_bounds__(128) void tc_z(int boff) {
    extern __shared__ char sm[];
    const int b = boff + blockIdx.z;
    const int bn = blockIdx.x*128, bm = blockIdx.y*128;
    FragC fc[4][4];
    core_row(sm, fc,
        g_gh + (size_t)b*EE_ + (size_t)bm*E_, g_gl + (size_t)b*EE_ + (size_t)bm*E_,
        g_wvh + bn, g_wvl + bn, E_, E_, E_/32);
    const int lane = threadIdx.x & 31, wid = threadIdx.x >> 5;
    const int wm = (wid >> 1)*64, wn = (wid & 1)*64;
    float* epi = (float*)sm + wid*256;
    __nv_bfloat16* Ch = g_zh + (size_t)b*EE_;
    __nv_bfloat16* Cl = g_zl + (size_t)b*EE_;
    for (int mi = 0; mi < 4; mi++)
        for (int nj = 0; nj < 4; nj++)
            frag_split_store(fc[mi][nj], epi, lane, Ch, Cl, E_,
                             bm + wm + mi*16, bn + wn + nj*16);
}

// ---------------- fused: M_h = Wk_h^T Z_h ; N_h = M_h @ W_h (split bf16) ----------------
__global__ __launch_bounds__(256) void gemm_mw(const float* __restrict__ lw, int boff) {
    int b = boff + blockIdx.x / HEADS_;
    int h = blockIdx.x % HEADS_;
    __shared__ float Ms[64*65];      // Ms[d*65 + row] = M[row][d] (transposed)
    __shared__ float buf[4224];      // phase1: As(2112) + Bs(2080); phase2: Ws(4096)
    float* As = buf;                 // [64][33]
    float* Bs = buf + 2112;          // [32][65]
    float* Ws = buf;                 // [64][64] (phase2 overlay)
    const int t = threadIdx.x;

    // ---- phase 1: M = Wk_h^T @ Z_h (64x64, K=768) ----
    {
        const int arow = t >> 2, ac8 = (t & 3)*8;
        const int brow = t >> 3, bj8 = (t & 7)*8;
        const int ty = t >> 4, tx = t & 15;
        float acc[4][4] = {};
        for (int e0 = 0; e0 < E_; e0 += 32) {
            for (int u = 0; u < 8; u++) {
                size_t ia = (size_t)(h*64 + arow)*E_ + e0 + ac8 + u;
                As[arow*33 + ac8 + u] = __bfloat162float(g_wkth[ia]) + __bfloat162float(g_wktl[ia]);
            }
            for (int u = 0; u < 8; u++) {
                size_t ib = (size_t)b*EE_ + (size_t)(e0 + brow)*E_ + h*64 + bj8 + u;
                Bs[brow*65 + bj8 + u] = __bfloat162float(g_zh[ib]) + __bfloat162float(g_zl[ib]);
            }
            __syncthreads();
            for (int e = 0; e < 32; e++) {
                float a[4], bb[4];
                for (int i = 0; i < 4; i++) a[i]  = As[(ty*4+i)*33 + e];
                for (int j = 0; j < 4; j++) bb[j] = Bs[e*65 + tx*4+j];
                for (int i = 0; i < 4; i++)
                    for (int j = 0; j < 4; j++) acc[i][j] += a[i]*bb[j];
            }
            __syncthreads();
        }
        // store transposed into Ms: Ms[col*65 + row]
        for (int i = 0; i < 4; i++)
            for (int j = 0; j < 4; j++)
                Ms[(tx*4+j)*65 + ty*4+i] = acc[i][j];
    }
    __syncthreads();

    // ---- phase 2: N_h = M @ W_h, twelve 64-col chunks, split-store bf16 ----
    const int ty2 = t >> 4, tx2 = t & 15;   // 16x16 threads; rows ty2*4, cols tx2*4
    for (int ct = 0; ct < 12; ct++) {
        for (int it = 0; it < 4; it++) {
            int id = t + it*256;             // 0..1023 float4s
            int d  = id >> 4;
            int c4 = (id & 15)*4;
            *(float4*)(Ws + d*64 + c4) =
                *(const float4*)(lw + (size_t)(h*64 + d)*E_ + ct*64 + c4);
        }
        __syncthreads();
        float acc2[4][4] = {};
        for (int d = 0; d < 64; d++) {
            float a[4], bb[4];
            for (int i = 0; i < 4; i++) a[i]  = Ms[d*65 + ty2*4+i];
            for (int j = 0; j < 4; j++) bb[j] = Ws[d*64 + tx2*4+j];
            for (int i = 0; i < 4; i++)
                for (int j = 0; j < 4; j++) acc2[i][j] += a[i]*bb[j];
        }
        for (int i = 0; i < 4; i++) {
            size_t o = (size_t)b*EE_ + (size_t)(h*64 + ty2*4+i)*E_ + ct*64 + tx2*4;
            float4 v = make_float4(acc2[i][0], acc2[i][1], acc2[i][2], acc2[i][3]);
            split_store_g(g_nh + o, g_nl + o, v);
        }
        __syncthreads();
    }
}

__global__ __launch_bounds__(128) void tc_c(int boff) {
    extern __shared__ char sm[];
    const int b = boff + blockIdx.z;
    const int bn = blockIdx.x*128, bm = blockIdx.y*128;
    FragC fc[4][4];
    core_row(sm, fc,
        g_wqh + (size_t)bm*E_, g_wql + (size_t)bm*E_,
        g_nh + (size_t)b*EE_ + bn, g_nl + (size_t)b*EE_ + bn, E_, E_, HID_/32);
    const int lane = threadIdx.x & 31, wid = threadIdx.x >> 5;
    const int wm = (wid >> 1)*64, wn = (wid & 1)*64;
    float* epi = (float*)sm + wid*256;
    __nv_bfloat16* Ch = g_ch + (size_t)b*EE_;
    __nv_bfloat16* Cl = g_cl + (size_t)b*EE_;
    for (int mi = 0; mi < 4; mi++)
        for (int nj = 0; nj < 4; nj++)
            frag_split_store(fc[mi][nj], epi, lane, Ch, Cl, E_,
                             bm + wm + mi*16, bn + wn + nj*16);
}

__global__ __launch_bounds__(128) void tc_final(
    const float* __restrict__ x, const float* __restrict__ lb,
    float* __restrict__ out, int boff) {
    extern __shared__ char sm[];
    const int b = boff + blockIdx.z;
    const int bn = blockIdx.x*128, bm = blockIdx.y*128;
    FragC fc[4][4];
    core_row(sm, fc,
        g_xh + (size_t)(b*P_ + bm)*E_, g_xl + (size_t)(b*P_ + bm)*E_,
        g_ch + (size_t)b*EE_ + bn, g_cl + (size_t)b*EE_ + bn, E_, E_, E_/32);
    const int lane = threadIdx.x & 31, wid = threadIdx.x >> 5;
    const int wm = (wid >> 1)*64, wn = (wid & 1)*64;
    float* epi = (float*)sm + wid*256;
    const int erow = lane >> 1, ecol = (lane & 1)*8;
    for (int mi = 0; mi < 4; mi++) {
        for (int nj = 0; nj < 4; nj++) {
            wmma::store_matrix_sync(epi, fc[mi][nj], 16, wmma::mem_row_major);
            __syncwarp();
            int row = bm + wm + mi*16 + erow;
            int cb  = bn + wn + nj*16 + ecol;
            const float* xr = x + (size_t)b*PE_ + (size_t)row*E_ + cb;
            float* orow = out + (size_t)b*PE_ + (size_t)row*E_ + cb;
            const float* ep = epi + erow*16 + ecol;
            float4 v0, v1;
            v0.x = fmaxf(ep[0] + lb[cb+0], 0.f) + xr[0];
            v0.y = fmaxf(ep[1] + lb[cb+1], 0.f) + xr[1];
            v0.z = fmaxf(ep[2] + lb[cb+2], 0.f) + xr[2];
            v0.w = fmaxf(ep[3] + lb[cb+3], 0.f) + xr[3];
            v1.x = fmaxf(ep[4] + lb[cb+4], 0.f) + xr[4];
            v1.y = fmaxf(ep[5] + lb[cb+5], 0.f) + xr[5];
            v1.z = fmaxf(ep[6] + lb[cb+6], 0.f) + xr[6];
            v1.w = fmaxf(ep[7] + lb[cb+7], 0.f) + xr[7];
            *(float4*)(orow + 0) = v0;
            *(float4*)(orow + 4) = v1;
            __syncwarp();
        }
    }
}

// ---------------- static stream setup (pre-main; warms all pools) ----------------
__global__ void warm_kernel() {}

static cudaStream_t g_streams[NSTREAM];
static cudaStream_t g_wstream;
static cudaEvent_t  g_ev_fork;
static cudaEvent_t  g_ev_w;
static cudaEvent_t  g_ev_join[NSTREAM];

struct StreamInit {
    StreamInit() {
        cudaFree(0);
        for (int i = 0; i < NSTREAM; i++) {
            cudaStreamCreateWithFlags(&g_streams[i], cudaStreamNonBlocking);
            cudaEventCreateWithFlags(&g_ev_join[i], cudaEventDisableTiming);
        }
        cudaStreamCreateWithFlags(&g_wstream, cudaStreamNonBlocking);
        cudaEventCreateWithFlags(&g_ev_fork, cudaEventDisableTiming);
        cudaEventCreateWithFlags(&g_ev_w, cudaEventDisableTiming);
        for (int rep = 0; rep < 2; rep++) {
            warm_kernel<<<1, 32>>>();
            cudaEventRecord(g_ev_fork, 0);
            cudaStreamWaitEvent(g_wstream, g_ev_fork, 0);
            warm_kernel<<<1, 32, 0, g_wstream>>>();
            cudaEventRecord(g_ev_w, g_wstream);
            for (int i = 0; i < NSTREAM; i++) {
                cudaStreamWaitEvent(g_streams[i], g_ev_fork, 0);
                warm_kernel<<<1, 32, 0, g_streams[i]>>>();
                cudaStreamWaitEvent(g_streams[i], g_ev_w, 0);
                warm_kernel<<<1, 32, 0, g_streams[i]>>>();
                cudaEventRecord(g_ev_join[i], g_streams[i]);
                cudaStreamWaitEvent(0, g_ev_join[i], 0);
            }
            warm_kernel<<<1, 32>>>();
        }
        cudaDeviceSynchronize();
    }
};
static StreamInit g_stream_init;

// ---------------- launch: 8 fully-parallel per-group chains + weight stream ----------------
extern "C" void kernel_launch(void* const* d_in, const int* in_sizes, int n_in,
                              void* d_out, int out_size) {
    (void)in_sizes; (void)n_in; (void)out_size;
    const float* x   = (const float*)d_in[0];
    const float* lnw = (const float*)d_in[1];
    const float* lnb = (const float*)d_in[2];
    const float* qkv = (const float*)d_in[3];
    const float* lw  = (const float*)d_in[4];
    const float* lb  = (const float*)d_in[5];
    float* out = (float*)d_out;

    cudaFuncSetAttribute(tc_gram,  cudaFuncAttributeMaxDynamicSharedMemorySize, COL_SMEM);
    cudaFuncSetAttribute(tc_z,     cudaFuncAttributeMaxDynamicSharedMemorySize, ROW_SMEM);
    cudaFuncSetAttribute(tc_c,     cudaFuncAttributeMaxDynamicSharedMemorySize, ROW_SMEM);
    cudaFuncSetAttribute(tc_final, cudaFuncAttributeMaxDynamicSharedMemorySize, ROW_SMEM);

    // fork immediately from the captured stream
    cudaEventRecord(g_ev_fork, 0);
    cudaStreamWaitEvent(g_wstream, g_ev_fork, 0);
    for (int i = 0; i < NSTREAM; i++)
        cudaStreamWaitEvent(g_streams[i], g_ev_fork, 0);

    // weight split on its own stream, overlapped with all LN chains
    split_w_all<<<dim3((EE_/4 + 255)/256, 3), 256, 0, g_wstream>>>(qkv);
    cudaEventRecord(g_ev_w, g_wstream);

    for (int i = 0; i < NSTREAM; i++) {
        int boff = i*BG_;
        cudaStream_t s = g_streams[i];
        ln_stats1<<<dim3(128, BG_), 256, 0, s>>>(x, boff);
        ln_stats2<<<BG_, 128, 0, s>>>(boff);
        split_xn<<<dim3(96, BG_), 256, 0, s>>>(x, lnw, lnb, boff);
        tc_gram <<<dim3(21, 1, BG_),          128, COL_SMEM, s>>>(boff);
        cudaStreamWaitEvent(s, g_ev_w, 0);   // weights needed from tc_z onward
        tc_z    <<<dim3(E_/128, E_/128, BG_), 128, ROW_SMEM, s>>>(boff);
        gemm_mw <<<BG_*HEADS_, 256, 0, s>>>(lw, boff);
        tc_c    <<<dim3(E_/128, E_/128, BG_), 128, ROW_SMEM, s>>>(boff);
        tc_final<<<dim3(E_/128, P_/128, BG_), 128, ROW_SMEM, s>>>(x, lb, out, boff);
    }

    // join back to the captured stream
    for (int i = 0; i < NSTREAM; i++) {
        cudaEventRecord(g_ev_join[i], g_streams[i]);
        cudaStreamWaitEvent(0, g_ev_join[i], 0);
    }
}